// round 15
// baseline (speedup 1.0000x reference)
#include <cuda_runtime.h>
#include <cstdint>

// ESSAttn: b=8, C=64, H=W=256, N=65536
// x, out: [b][C][N]  (b<<22 | c<<16 | n)
// scratch q2n,k2d,v: [b][N][C]  (b<<22 | n<<6 | c)

#define NPIX 65536
#define NBAT 8

typedef unsigned long long u64;

// ---------------- scratch ----------------
__device__ float g_q2n[(size_t)NBAT * 64 * NPIX];
__device__ float g_k2d[(size_t)NBAT * 64 * NPIX];
__device__ float g_v  [(size_t)NBAT * 64 * NPIX];
__device__ float g_M  [NBAT * 64 * 64];
__device__ float g_css[NBAT * 64];
__device__ float g_WcT[NBAT * 128 * 64];   // [b][k][j] k-major concat weight (out)
__device__ u64   g_WqD[3 * 64 * 64];       // [pass][j][k] dup'd qkv weights (w,w)

// ---------------- packed fp32 + async helpers ----------------
__device__ __forceinline__ u64 ffma2(u64 a, u64 b, u64 c) {
    u64 d;
    asm("fma.rn.f32x2 %0, %1, %2, %3;" : "=l"(d) : "l"(a), "l"(b), "l"(c));
    return d;
}
__device__ __forceinline__ u64 fadd2(u64 a, u64 b) {
    u64 d;
    asm("add.rn.f32x2 %0, %1, %2;" : "=l"(d) : "l"(a), "l"(b));
    return d;
}
__device__ __forceinline__ float2 unpack2(u64 v) {
    float lo, hi;
    asm("mov.b64 {%0, %1}, %2;" : "=f"(lo), "=f"(hi) : "l"(v));
    return make_float2(lo, hi);
}
__device__ __forceinline__ u64 dup2(float f) {
    u64 d;
    asm("mov.b64 %0, {%1, %1};" : "=l"(d) : "f"(f));
    return d;
}
__device__ __forceinline__ float hsum2(u64 a, u64 b) {
    float2 r = unpack2(fadd2(a, b));
    return r.x + r.y;
}
__device__ __forceinline__ u64 lds_u64(const float* p) {
    return *reinterpret_cast<const u64*>(p);
}
__device__ __forceinline__ ulonglong2 lds_u128(const float* p) {
    return *reinterpret_cast<const ulonglong2*>(p);
}
__device__ __forceinline__ uint32_t smem_u32(const void* p) {
    uint32_t a;
    asm("{ .reg .u64 t; cvta.to.shared.u64 t, %1; cvt.u32.u64 %0, t; }" : "=r"(a) : "l"(p));
    return a;
}
__device__ __forceinline__ void cpa16(uint32_t dst, const float* src) {
    asm volatile("cp.async.cg.shared.global [%0], [%1], 16;" :: "r"(dst), "l"(src));
}
#define CPA_COMMIT() asm volatile("cp.async.commit_group;" ::: "memory")
#define CPA_WAIT(n)  asm volatile("cp.async.wait_group %0;" :: "n"(n) : "memory")

// ---------------------------------------------------------------------------
// prep: build dup'd qkv weights g_WqD[p][j][k] = (w,w); zero accumulators
__global__ void essa_prep(const float* __restrict__ wqkv) {
    int i = blockIdx.x * 256 + threadIdx.x;   // grid 128 -> 32768
    if (i < 12288) {
        float w = wqkv[i];                    // i = (p*64+j)*64 + k
        g_WqD[i] = dup2(w);
    }
    if (i < NBAT * 64 * 64) g_M[i] = 0.f;
    if (i < NBAT * 64)      g_css[i] = 0.f;
}

// ---------------------------------------------------------------------------
// qkv (px-packed, dup'd-W): 256 thr/CTA, 128 px, 3 passes of 64 outputs.
// tx=tid&31, ty=tid>>5 (warp==ty). acc[pq][jj] = (out(px0),out(px0+1)),
// px0 = 2*(tx+32*pq), j = 8*ty+jj. A[k][px] pad 132; Wd[j][k] u64 dups
// (broadcast LDS.128, no dup MOVs). Single Wd buffer, reloaded via cp.async
// overlapped with the stats phase.
// smem bytes: A 33792 | Wd 32768 | C 33280 | sB 768 -> 100608
__global__ __launch_bounds__(256) void essa_qkv(const float* __restrict__ x,
                                                const float* __restrict__ bqkv) {
    extern __shared__ float sm[];
    float* A  = sm;                               // 8448 fl
    u64*   Wd = (u64*)(sm + 8448);                // 4096 u64
    float* C  = sm + 16640;                       // 8320 fl
    float* sB = sm + 24960;                       // 192 fl

    const int tid = threadIdx.x;
    const int tx = tid & 31, ty = tid >> 5;
    const int b = blockIdx.y;
    const int n0 = blockIdx.x << 7;
    const size_t base = (size_t)b << 22;
    const uint32_t A32 = smem_u32(A), Wd32 = smem_u32(Wd);

    // initial loads: A (row copies from x [c][n]) + Wd slab 0
    for (int i = tid; i < 2048; i += 256) {
        int k = i >> 5, ck = (i & 31) << 2;
        cpa16(A32 + (k * 132 + ck) * 4, x + base + ((size_t)k << 16) + n0 + ck);
    }
    for (int i = tid; i < 2048; i += 256)
        cpa16(Wd32 + i * 16, (const float*)g_WqD + i * 4);
    CPA_COMMIT();
    if (tid < 48) *(float4*)(sB + tid * 4) = *(const float4*)(bqkv + tid * 4);
    CPA_WAIT(0);
    __syncthreads();

    // stats mapping: 2 threads per pixel (partner = tid^1, same warp)
    const int spx = tid >> 1;
    const int h = tid & 1;

    u64 acc[2][8];

#pragma unroll 1
    for (int pass = 0; pass < 3; ++pass) {
        // ---- GEMM: dup-free inner loop ----
#pragma unroll
        for (int pq = 0; pq < 2; ++pq)
#pragma unroll
            for (int jj = 0; jj < 8; ++jj) acc[pq][jj] = 0;
#pragma unroll 2
        for (int k4 = 0; k4 < 16; ++k4) {
            u64 av[4][2];
#pragma unroll
            for (int kk = 0; kk < 4; ++kk)
#pragma unroll
                for (int pq = 0; pq < 2; ++pq)
                    av[kk][pq] = lds_u64(A + (4 * k4 + kk) * 132 + 2 * (tx + 32 * pq));
#pragma unroll
            for (int jj = 0; jj < 8; ++jj) {
                const u64* wrow = Wd + (8 * ty + jj) * 64 + 4 * k4;
                ulonglong2 w01 = *(const ulonglong2*)(wrow);
                ulonglong2 w23 = *(const ulonglong2*)(wrow + 2);
#pragma unroll
                for (int pq = 0; pq < 2; ++pq) {
                    acc[pq][jj] = ffma2(av[0][pq], w01.x, acc[pq][jj]);
                    acc[pq][jj] = ffma2(av[1][pq], w01.y, acc[pq][jj]);
                    acc[pq][jj] = ffma2(av[2][pq], w23.x, acc[pq][jj]);
                    acc[pq][jj] = ffma2(av[3][pq], w23.y, acc[pq][jj]);
                }
            }
        }
        __syncthreads();   // all warps done reading Wd (and prior stats done)

        if (pass < 2) {
            // prefetch next W slab into Wd (overlaps staging + stats)
            {
                const float* src = (const float*)(g_WqD + (size_t)(pass + 1) * 4096);
                for (int i = tid; i < 2048; i += 256)
                    cpa16(Wd32 + i * 16, src + i * 4);
                CPA_COMMIT();
            }
            // stage C[j][px] pad 130 (STS.64)
#pragma unroll
            for (int jj = 0; jj < 8; ++jj)
#pragma unroll
                for (int pq = 0; pq < 2; ++pq)
                    *(u64*)(C + (8 * ty + jj) * 130 + 2 * (tx + 32 * pq)) = acc[pq][jj];
            __syncthreads();

            // stats: thread handles channels h*32..h*32+31 of pixel spx
            {
                const int boff = pass * 64, j0 = h << 5;
                const size_t rownc = base + ((size_t)(n0 + spx) << 6);
                float rv[32];
                float part = 0.f;
#pragma unroll
                for (int t = 0; t < 32; ++t) {
                    rv[t] = C[(j0 + t) * 130 + spx] + sB[boff + j0 + t];
                    part += rv[t];
                }
                float mean = (part + __shfl_xor_sync(0xFFFFFFFFu, part, 1)) * (1.f / 64.f);
                float ss = 0.f;
#pragma unroll
                for (int t = 0; t < 32; ++t) {
                    float u = rv[t] - mean;
                    u = u * u;
                    rv[t] = u;
                    ss += u;
                }
                ss += __shfl_xor_sync(0xFFFFFFFFu, ss, 1);
                float inv = 1.f / (ss + 1e-7f);
                float scale;
                if (pass == 0) {
                    float nr = 0.f;
#pragma unroll
                    for (int t = 0; t < 32; ++t) {
                        float u = rv[t] * inv;
                        nr = fmaf(u, u, nr);
                    }
                    nr += __shfl_xor_sync(0xFFFFFFFFu, nr, 1);
                    scale = inv / fmaxf(sqrtf(nr), 1e-12f);
                } else {
                    scale = inv;
                }
                float* dst = (pass == 0 ? g_q2n : g_k2d) + rownc + j0;
#pragma unroll
                for (int t = 0; t < 8; ++t)
                    reinterpret_cast<float4*>(dst)[t] =
                        make_float4(rv[4 * t] * scale, rv[4 * t + 1] * scale,
                                    rv[4 * t + 2] * scale, rv[4 * t + 3] * scale);
            }
            CPA_WAIT(0);
            __syncthreads();
        } else {
            // V: assemble float4 rows from packed acc -> g_v [n][c]
            float bs[8];
#pragma unroll
            for (int jj = 0; jj < 8; ++jj) bs[jj] = sB[128 + 8 * ty + jj];
#pragma unroll
            for (int pq = 0; pq < 2; ++pq) {
                const int n = n0 + 2 * (tx + 32 * pq);
                float* dst = g_v + base + ((size_t)n << 6) + 8 * ty;
                float2 u0 = unpack2(acc[pq][0]), u1 = unpack2(acc[pq][1]);
                float2 u2 = unpack2(acc[pq][2]), u3 = unpack2(acc[pq][3]);
                float2 u4 = unpack2(acc[pq][4]), u5 = unpack2(acc[pq][5]);
                float2 u6 = unpack2(acc[pq][6]), u7 = unpack2(acc[pq][7]);
                *(float4*)(dst)      = make_float4(u0.x + bs[0], u1.x + bs[1], u2.x + bs[2], u3.x + bs[3]);
                *(float4*)(dst + 4)  = make_float4(u4.x + bs[4], u5.x + bs[5], u6.x + bs[6], u7.x + bs[7]);
                *(float4*)(dst + 64) = make_float4(u0.y + bs[0], u1.y + bs[1], u2.y + bs[2], u3.y + bs[3]);
                *(float4*)(dst + 68) = make_float4(u4.y + bs[4], u5.y + bs[5], u6.y + bs[6], u7.y + bs[7]);
            }
        }
    }
}

// ---------------------------------------------------------------------------
// kvacc: reg-prefetch, FFMA2 (unchanged; at FFMA2-pipe floor)
__global__ __launch_bounds__(256) void essa_kvacc() {
    const int b = blockIdx.y;
    const int n0 = blockIdx.x << 9;
    const size_t base = (size_t)b << 22;

    __shared__ float ks[64 * 33];
    __shared__ __align__(16) float vs[32 * 68];

    const int tid = threadIdx.x;
    const int ty = tid >> 4, tx = tid & 15;
    const int c0 = ty << 2, d0 = tx << 2;

    const int nnA = tid >> 4, c4A = (tid & 15) << 2;
    const int i1 = tid + 256;
    const int nnB = i1 >> 4, c4B = (i1 & 15) << 2;

    u64 acc[4][2];
#pragma unroll
    for (int i = 0; i < 4; ++i) { acc[i][0] = 0; acc[i][1] = 0; }
    float cssr = 0.f;

    float4 ka, va, kb, vb;
    {
        size_t gA = base + ((size_t)(n0 + nnA) << 6) + c4A;
        size_t gB = base + ((size_t)(n0 + nnB) << 6) + c4B;
        ka = *reinterpret_cast<const float4*>(g_k2d + gA);
        va = *reinterpret_cast<const float4*>(g_v + gA);
        kb = *reinterpret_cast<const float4*>(g_k2d + gB);
        vb = *reinterpret_cast<const float4*>(g_v + gB);
    }

#pragma unroll 1
    for (int t = 0; t < 16; ++t) {
        __syncthreads();
        ks[(c4A + 0) * 33 + nnA] = ka.x;
        ks[(c4A + 1) * 33 + nnA] = ka.y;
        ks[(c4A + 2) * 33 + nnA] = ka.z;
        ks[(c4A + 3) * 33 + nnA] = ka.w;
        *reinterpret_cast<float4*>(vs + nnA * 68 + c4A) = va;
        ks[(c4B + 0) * 33 + nnB] = kb.x;
        ks[(c4B + 1) * 33 + nnB] = kb.y;
        ks[(c4B + 2) * 33 + nnB] = kb.z;
        ks[(c4B + 3) * 33 + nnB] = kb.w;
        *reinterpret_cast<float4*>(vs + nnB * 68 + c4B) = vb;
        if (t < 15) {
            const int nb = n0 + ((t + 1) << 5);
            size_t gA = base + ((size_t)(nb + nnA) << 6) + c4A;
            size_t gB = base + ((size_t)(nb + nnB) << 6) + c4B;
            ka = *reinterpret_cast<const float4*>(g_k2d + gA);
            va = *reinterpret_cast<const float4*>(g_v + gA);
            kb = *reinterpret_cast<const float4*>(g_k2d + gB);
            vb = *reinterpret_cast<const float4*>(g_v + gB);
        }
        __syncthreads();
        const float* kp = ks + c0 * 33;
#pragma unroll 4
        for (int nn = 0; nn < 32; ++nn) {
            ulonglong2 v01 = *reinterpret_cast<const ulonglong2*>(vs + nn * 68 + d0);
            float k0 = kp[nn], k1 = kp[33 + nn], k2 = kp[66 + nn], k3 = kp[99 + nn];
            u64 kk0 = dup2(k0), kk1 = dup2(k1), kk2 = dup2(k2), kk3 = dup2(k3);
            acc[0][0] = ffma2(kk0, v01.x, acc[0][0]); acc[0][1] = ffma2(kk0, v01.y, acc[0][1]);
            acc[1][0] = ffma2(kk1, v01.x, acc[1][0]); acc[1][1] = ffma2(kk1, v01.y, acc[1][1]);
            acc[2][0] = ffma2(kk2, v01.x, acc[2][0]); acc[2][1] = ffma2(kk2, v01.y, acc[2][1]);
            acc[3][0] = ffma2(kk3, v01.x, acc[3][0]); acc[3][1] = ffma2(kk3, v01.y, acc[3][1]);
        }
        if (tid < 64) {
            const float* cp = ks + tid * 33;
#pragma unroll 8
            for (int nn = 0; nn < 32; ++nn) { float u = cp[nn]; cssr = fmaf(u, u, cssr); }
        }
    }

    float* Mp = g_M + (b << 12);
#pragma unroll
    for (int i = 0; i < 4; ++i) {
        float2 a0 = unpack2(acc[i][0]), a1 = unpack2(acc[i][1]);
        atomicAdd(&Mp[(c0 + i) * 64 + d0 + 0], a0.x);
        atomicAdd(&Mp[(c0 + i) * 64 + d0 + 1], a0.y);
        atomicAdd(&Mp[(c0 + i) * 64 + d0 + 2], a1.x);
        atomicAdd(&Mp[(c0 + i) * 64 + d0 + 3], a1.y);
    }
    if (tid < 64) atomicAdd(&g_css[(b << 6) + tid], cssr);
}

// ---------------------------------------------------------------------------
// wcat: emit k-major concat weight WcT[b][k][j] (unchanged)
__global__ void essa_wcat(const float* __restrict__ wln) {
    __shared__ float sM[4096], sW[4096], sInv[64];
    const int b = blockIdx.x;
    const int tid = threadIdx.x;

    for (int i = tid; i < 4096; i += 256) {
        sM[i] = g_M[(b << 12) + i];
        sW[i] = wln[i];
    }
    if (tid < 64)
        sInv[tid] = 1.f / (fmaxf(sqrtf(g_css[(b << 6) + tid]), 1e-12f) * 256.f);
    __syncthreads();

    float* Wc = g_WcT + (b << 13);
    for (int i = tid; i < 4096; i += 256) {
        int k = i >> 6, j = i & 63;
        Wc[k * 64 + j] = sW[j * 64 + k];
    }
#pragma unroll 1
    for (int t = 0; t < 16; ++t) {
        int i = tid + (t << 8);
        int c = i >> 6, j = i & 63;
        u64 s0 = 0, s1 = 0;
#pragma unroll
        for (int dd = 0; dd < 16; ++dd) {
            s0 = ffma2(lds_u64(sM + c * 64 + 4 * dd),     lds_u64(sW + j * 64 + 4 * dd),     s0);
            s1 = ffma2(lds_u64(sM + c * 64 + 4 * dd + 2), lds_u64(sW + j * 64 + 4 * dd + 2), s1);
        }
        Wc[(64 + c) * 64 + j] = hsum2(s0, s1) * sInv[c];
    }
}

// ---------------------------------------------------------------------------
// out GEMM core (128 thr, j-packing, measured-best R11)
__device__ __forceinline__ void gemm_j(const float* __restrict__ A,
                                       const float* __restrict__ Wt,
                                       int tx, int ty, int k4lo, int k4hi,
                                       u64 acc[8][4]) {
#pragma unroll 2
    for (int k4 = k4lo; k4 < k4hi; ++k4) {
        ulonglong2 bt0[4], bt1[4];
#pragma unroll
        for (int kk = 0; kk < 4; ++kk) {
            bt0[kk] = lds_u128(Wt + (4 * k4 + kk) * 64 + 8 * ty);
            bt1[kk] = lds_u128(Wt + (4 * k4 + kk) * 64 + 8 * ty + 4);
        }
#pragma unroll
        for (int pp = 0; pp < 8; ++pp) {
            ulonglong2 a = lds_u128(A + (tx + 16 * pp) * 132 + 4 * k4);
            float2 al = unpack2(a.x), ah = unpack2(a.y);
            u64 d0 = dup2(al.x), d1 = dup2(al.y), d2 = dup2(ah.x), d3 = dup2(ah.y);
            acc[pp][0] = ffma2(d0, bt0[0].x, acc[pp][0]);
            acc[pp][1] = ffma2(d0, bt0[0].y, acc[pp][1]);
            acc[pp][2] = ffma2(d0, bt1[0].x, acc[pp][2]);
            acc[pp][3] = ffma2(d0, bt1[0].y, acc[pp][3]);
            acc[pp][0] = ffma2(d1, bt0[1].x, acc[pp][0]);
            acc[pp][1] = ffma2(d1, bt0[1].y, acc[pp][1]);
            acc[pp][2] = ffma2(d1, bt1[1].x, acc[pp][2]);
            acc[pp][3] = ffma2(d1, bt1[1].y, acc[pp][3]);
            acc[pp][0] = ffma2(d2, bt0[2].x, acc[pp][0]);
            acc[pp][1] = ffma2(d2, bt0[2].y, acc[pp][1]);
            acc[pp][2] = ffma2(d2, bt1[2].x, acc[pp][2]);
            acc[pp][3] = ffma2(d2, bt1[2].y, acc[pp][3]);
            acc[pp][0] = ffma2(d3, bt0[3].x, acc[pp][0]);
            acc[pp][1] = ffma2(d3, bt0[3].y, acc[pp][1]);
            acc[pp][2] = ffma2(d3, bt1[3].x, acc[pp][2]);
            acc[pp][3] = ffma2(d3, bt1[3].y, acc[pp][3]);
        }
    }
}

// ---------------------------------------------------------------------------
// out: K=128 GEMM out[n][j] = [v|q2n][n][:] . WcT[:][j] + bln[j]  (unchanged R11)
__global__ __launch_bounds__(128) void essa_out(const float* __restrict__ bln,
                                                float* __restrict__ out) {
    extern __shared__ float sm[];
    float* A   = sm;
    float* Wt  = sm + 16896;
    float* sBl = sm + 25088;
    float* C   = sm;   // overlay

    const int tid = threadIdx.x;
    const int tx = tid & 15, ty = tid >> 4;
    const int b = blockIdx.y;
    const int n0 = blockIdx.x << 7;
    const size_t base = (size_t)b << 22;
    const uint32_t A32 = smem_u32(A), Wt32 = smem_u32(Wt), B32 = smem_u32(sBl);
    const float* Ws = g_WcT + (b << 13);

    for (int i = tid; i < 2048; i += 128) {
        int px = i >> 4, ck = (i & 15) << 2;
        cpa16(A32 + (px * 132 + ck) * 4, g_v + base + ((size_t)(n0 + px) << 6) + ck);
    }
    for (int i = tid; i < 1024; i += 128) {
        int k = i >> 4, ck = (i & 15) << 2;
        cpa16(Wt32 + (k * 64 + ck) * 4, Ws + k * 64 + ck);
    }
    if (tid < 16) cpa16(B32 + tid * 16, bln + tid * 4);
    CPA_COMMIT();
    for (int i = tid; i < 2048; i += 128) {
        int px = i >> 4, ck = (i & 15) << 2;
        cpa16(A32 + (px * 132 + 64 + ck) * 4, g_q2n + base + ((size_t)(n0 + px) << 6) + ck);
    }
    for (int i = tid; i < 1024; i += 128) {
        int k = i >> 4, ck = (i & 15) << 2;
        cpa16(Wt32 + ((64 + k) * 64 + ck) * 4, Ws + (64 + k) * 64 + ck);
    }
    CPA_COMMIT();

    u64 acc[8][4];
#pragma unroll
    for (int pp = 0; pp < 8; ++pp)
#pragma unroll
        for (int jq = 0; jq < 4; ++jq) acc[pp][jq] = 0;

    CPA_WAIT(1);
    __syncthreads();
    gemm_j(A, Wt, tx, ty, 0, 16, acc);
    CPA_WAIT(0);
    __syncthreads();
    gemm_j(A, Wt, tx, ty, 16, 32, acc);
    __syncthreads();

#pragma unroll
    for (int pp = 0; pp < 8; ++pp)
#pragma unroll
        for (int jq = 0; jq < 4; ++jq)
            *(u64*)(C + (tx + 16 * pp) * 66 + 8 * ty + 2 * jq) = acc[pp][jq];
    __syncthreads();

    for (int i = tid; i < 8192; i += 128) {
        int j = i >> 7, px = i & 127;
        out[base + ((size_t)j << 16) + n0 + px] = C[px * 66 + j] + sBl[j];
    }
}

// ---------------------------------------------------------------------------
extern "C" void kernel_launch(void* const* d_in, const int* in_sizes, int n_in,
                              void* d_out, int out_size) {
    const float* x    = (const float*)d_in[0];
    const float* wqkv = (const float*)d_in[1];
    const float* bqkv = (const float*)d_in[2];
    const float* wln  = (const float*)d_in[3];
    const float* bln  = (const float*)d_in[4];
    float* out = (float*)d_out;

    cudaFuncSetAttribute(essa_qkv, cudaFuncAttributeMaxDynamicSharedMemorySize, 100608);
    cudaFuncSetAttribute(essa_out, cudaFuncAttributeMaxDynamicSharedMemorySize, 100608);

    essa_prep<<<128, 256>>>(wqkv);

    dim3 gridQ(NPIX / 128, NBAT);
    essa_qkv<<<gridQ, 256, 100608>>>(x, bqkv);

    dim3 gridM(NPIX / 512, NBAT);
    essa_kvacc<<<gridM, 256>>>();

    essa_wcat<<<NBAT, 256>>>(wln);

    essa_out<<<gridQ, 128, 100608>>>(bln, out);
}

// round 16
// speedup vs baseline: 1.0718x; 1.0718x over previous
#include <cuda_runtime.h>
#include <cstdint>

// ESSAttn: b=8, C=64, H=W=256, N=65536
// x, out: [b][C][N]  (b<<22 | c<<16 | n)
// scratch q2n,k2d,v: [b][N][C]  (b<<22 | n<<6 | c)

#define NPIX 65536
#define NBAT 8

typedef unsigned long long u64;

// ---------------- scratch ----------------
__device__ float g_q2n[(size_t)NBAT * 64 * NPIX];
__device__ float g_k2d[(size_t)NBAT * 64 * NPIX];
__device__ float g_v  [(size_t)NBAT * 64 * NPIX];
__device__ float g_M  [NBAT * 64 * 64];
__device__ float g_css[NBAT * 64];
__device__ float g_WcT[NBAT * 128 * 64];   // [b][k][j] k-major concat weight (out)

// ---------------- packed fp32 + async helpers ----------------
__device__ __forceinline__ u64 ffma2(u64 a, u64 b, u64 c) {
    u64 d;
    asm("fma.rn.f32x2 %0, %1, %2, %3;" : "=l"(d) : "l"(a), "l"(b), "l"(c));
    return d;
}
__device__ __forceinline__ u64 fadd2(u64 a, u64 b) {
    u64 d;
    asm("add.rn.f32x2 %0, %1, %2;" : "=l"(d) : "l"(a), "l"(b));
    return d;
}
__device__ __forceinline__ float2 unpack2(u64 v) {
    float lo, hi;
    asm("mov.b64 {%0, %1}, %2;" : "=f"(lo), "=f"(hi) : "l"(v));
    return make_float2(lo, hi);
}
__device__ __forceinline__ u64 dup2(float f) {
    u64 d;
    asm("mov.b64 %0, {%1, %1};" : "=l"(d) : "f"(f));
    return d;
}
__device__ __forceinline__ float hsum2(u64 a, u64 b) {
    float2 r = unpack2(fadd2(a, b));
    return r.x + r.y;
}
__device__ __forceinline__ u64 lds_u64(const float* p) {
    return *reinterpret_cast<const u64*>(p);
}
__device__ __forceinline__ ulonglong2 lds_u128(const float* p) {
    return *reinterpret_cast<const ulonglong2*>(p);
}
__device__ __forceinline__ uint32_t smem_u32(const void* p) {
    uint32_t a;
    asm("{ .reg .u64 t; cvta.to.shared.u64 t, %1; cvt.u32.u64 %0, t; }" : "=r"(a) : "l"(p));
    return a;
}
__device__ __forceinline__ void cpa16(uint32_t dst, const float* src) {
    asm volatile("cp.async.cg.shared.global [%0], [%1], 16;" :: "r"(dst), "l"(src));
}
#define CPA_COMMIT() asm volatile("cp.async.commit_group;" ::: "memory")
#define CPA_WAIT(n)  asm volatile("cp.async.wait_group %0;" :: "n"(n) : "memory")

// ---------------------------------------------------------------------------
// qkv GEMM core (256 thr, px-packing): tx=tid&31, ty=tid>>5 (warp==ty).
// acc[pq][jj] = (out(px0), out(px0+1)), px0 = 2*(tx+32*pq), j = 8*ty+jj.
// A[k][px] pad 132, W[j][k] rows of 64. B loads are whole-warp broadcasts.
__device__ __forceinline__ void gemm_px(const float* __restrict__ A,
                                        const float* __restrict__ W,
                                        int tx, int ty, u64 acc[2][8]) {
#pragma unroll
    for (int pq = 0; pq < 2; ++pq)
#pragma unroll
        for (int jj = 0; jj < 8; ++jj) acc[pq][jj] = 0;
#pragma unroll 2
    for (int k4 = 0; k4 < 16; ++k4) {
        u64 av[4][2];   // [kk][pq]
#pragma unroll
        for (int kk = 0; kk < 4; ++kk)
#pragma unroll
            for (int pq = 0; pq < 2; ++pq)
                av[kk][pq] = lds_u64(A + (4 * k4 + kk) * 132 + 2 * (tx + 32 * pq));
#pragma unroll
        for (int jj = 0; jj < 8; ++jj) {
            ulonglong2 bb = lds_u128(W + (8 * ty + jj) * 64 + 4 * k4);
            float2 bl = unpack2(bb.x), bh = unpack2(bb.y);
            u64 d0 = dup2(bl.x), d1 = dup2(bl.y), d2 = dup2(bh.x), d3 = dup2(bh.y);
#pragma unroll
            for (int pq = 0; pq < 2; ++pq) {
                acc[pq][jj] = ffma2(av[0][pq], d0, acc[pq][jj]);
                acc[pq][jj] = ffma2(av[1][pq], d1, acc[pq][jj]);
                acc[pq][jj] = ffma2(av[2][pq], d2, acc[pq][jj]);
                acc[pq][jj] = ffma2(av[3][pq], d3, acc[pq][jj]);
            }
        }
    }
}

// ---------------------------------------------------------------------------
// qkv: 256 thr/CTA, 128 px, 3 passes of 64 outputs (R13 measured-best, exact).
// smem fl: A[64*132]=8448 | W0 4096 | W1 4096 | C[64*130]=8320 | sB 192 -> 100608 B
__global__ __launch_bounds__(256) void essa_qkv(const float* __restrict__ x,
                                                const float* __restrict__ wqkv,
                                                const float* __restrict__ bqkv) {
    extern __shared__ float sm[];
    float* A  = sm;
    float* W0 = sm + 8448;
    float* W1 = sm + 12544;
    float* C  = sm + 16640;
    float* sB = sm + 24960;

    const int tid = threadIdx.x;
    const int tx = tid & 31, ty = tid >> 5;
    const int b = blockIdx.y;
    const int n0 = blockIdx.x << 7;
    const size_t base = (size_t)b << 22;
    const uint32_t A32 = smem_u32(A), W032 = smem_u32(W0), W132 = smem_u32(W1);

    if (blockIdx.x == 0 && b == 0) {
        for (int i = tid; i < NBAT * 64 * 64; i += 256) g_M[i] = 0.f;
        for (int i = tid; i < NBAT * 64; i += 256) g_css[i] = 0.f;
    }

    // G0: A rows (row copy from x [c][n]; 64 rows x 32 chunks) + W(Q)
    for (int i = tid; i < 2048; i += 256) {
        int k = i >> 5, ck = (i & 31) << 2;
        cpa16(A32 + (k * 132 + ck) * 4, x + base + ((size_t)k << 16) + n0 + ck);
    }
    for (int i = tid; i < 1024; i += 256) {
        int j = i >> 4, ck = (i & 15) << 2;
        cpa16(W032 + (j * 64 + ck) * 4, wqkv + j * 64 + ck);
    }
    CPA_COMMIT();
    // G1: W(K)
    for (int i = tid; i < 1024; i += 256) {
        int j = i >> 4, ck = (i & 15) << 2;
        cpa16(W132 + (j * 64 + ck) * 4, wqkv + 4096 + j * 64 + ck);
    }
    CPA_COMMIT();
    if (tid < 48) *(float4*)(sB + tid * 4) = *(const float4*)(bqkv + tid * 4);
    CPA_WAIT(1);
    __syncthreads();

    // stats mapping: 2 threads per pixel (partner = tid^1, same warp)
    const int spx = tid >> 1;
    const int h = tid & 1;

    u64 acc[2][8];

#pragma unroll 1
    for (int pass = 0; pass < 3; ++pass) {
        gemm_px(A, (pass == 1) ? W1 : W0, tx, ty, acc);

        if (pass < 2) {
            __syncthreads();   // all warps done reading current W buffer
            if (pass == 0) {   // V weights -> W0
                for (int i = tid; i < 1024; i += 256) {
                    int j = i >> 4, ck = (i & 15) << 2;
                    cpa16(W032 + (j * 64 + ck) * 4, wqkv + 8192 + j * 64 + ck);
                }
                CPA_COMMIT();
            }
            // stage C[j][px] pad 130 (STS.64)
#pragma unroll
            for (int jj = 0; jj < 8; ++jj)
#pragma unroll
                for (int pq = 0; pq < 2; ++pq)
                    *(u64*)(C + (8 * ty + jj) * 130 + 2 * (tx + 32 * pq)) = acc[pq][jj];
            __syncthreads();

            // stats: thread handles channels h*32..h*32+31 of pixel spx
            {
                const int boff = pass * 64, j0 = h << 5;
                const size_t rownc = base + ((size_t)(n0 + spx) << 6);
                float rv[32];
                float part = 0.f;
#pragma unroll
                for (int t = 0; t < 32; ++t) {
                    rv[t] = C[(j0 + t) * 130 + spx] + sB[boff + j0 + t];
                    part += rv[t];
                }
                float mean = (part + __shfl_xor_sync(0xFFFFFFFFu, part, 1)) * (1.f / 64.f);
                float ss = 0.f;
#pragma unroll
                for (int t = 0; t < 32; ++t) {
                    float u = rv[t] - mean;
                    u = u * u;
                    rv[t] = u;
                    ss += u;
                }
                ss += __shfl_xor_sync(0xFFFFFFFFu, ss, 1);
                float inv = 1.f / (ss + 1e-7f);
                float scale;
                if (pass == 0) {
                    float nr = 0.f;
#pragma unroll
                    for (int t = 0; t < 32; ++t) {
                        float u = rv[t] * inv;
                        nr = fmaf(u, u, nr);
                    }
                    nr += __shfl_xor_sync(0xFFFFFFFFu, nr, 1);
                    scale = inv / fmaxf(sqrtf(nr), 1e-12f);
                } else {
                    scale = inv;
                }
                float* dst = (pass == 0 ? g_q2n : g_k2d) + rownc + j0;
#pragma unroll
                for (int t = 0; t < 8; ++t)
                    reinterpret_cast<float4*>(dst)[t] =
                        make_float4(rv[4 * t] * scale, rv[4 * t + 1] * scale,
                                    rv[4 * t + 2] * scale, rv[4 * t + 3] * scale);
            }
            if (pass == 0) { CPA_WAIT(1); } else { CPA_WAIT(0); }
            __syncthreads();
        } else {
            // V: assemble float4 rows from packed acc -> g_v [n][c]
            float bs[8];
#pragma unroll
            for (int jj = 0; jj < 8; ++jj) bs[jj] = sB[128 + 8 * ty + jj];
#pragma unroll
            for (int pq = 0; pq < 2; ++pq) {
                const int n = n0 + 2 * (tx + 32 * pq);
                float* dst = g_v + base + ((size_t)n << 6) + 8 * ty;
                float2 u0 = unpack2(acc[pq][0]), u1 = unpack2(acc[pq][1]);
                float2 u2 = unpack2(acc[pq][2]), u3 = unpack2(acc[pq][3]);
                float2 u4 = unpack2(acc[pq][4]), u5 = unpack2(acc[pq][5]);
                float2 u6 = unpack2(acc[pq][6]), u7 = unpack2(acc[pq][7]);
                *(float4*)(dst)      = make_float4(u0.x + bs[0], u1.x + bs[1], u2.x + bs[2], u3.x + bs[3]);
                *(float4*)(dst + 4)  = make_float4(u4.x + bs[4], u5.x + bs[5], u6.x + bs[6], u7.x + bs[7]);
                *(float4*)(dst + 64) = make_float4(u0.y + bs[0], u1.y + bs[1], u2.y + bs[2], u3.y + bs[3]);
                *(float4*)(dst + 68) = make_float4(u4.y + bs[4], u5.y + bs[5], u6.y + bs[6], u7.y + bs[7]);
            }
        }
    }
}

// ---------------------------------------------------------------------------
// kvacc: reg-prefetch, FFMA2 (unchanged)
__global__ __launch_bounds__(256) void essa_kvacc() {
    const int b = blockIdx.y;
    const int n0 = blockIdx.x << 9;
    const size_t base = (size_t)b << 22;

    __shared__ float ks[64 * 33];
    __shared__ __align__(16) float vs[32 * 68];

    const int tid = threadIdx.x;
    const int ty = tid >> 4, tx = tid & 15;
    const int c0 = ty << 2, d0 = tx << 2;

    const int nnA = tid >> 4, c4A = (tid & 15) << 2;
    const int i1 = tid + 256;
    const int nnB = i1 >> 4, c4B = (i1 & 15) << 2;

    u64 acc[4][2];
#pragma unroll
    for (int i = 0; i < 4; ++i) { acc[i][0] = 0; acc[i][1] = 0; }
    float cssr = 0.f;

    float4 ka, va, kb, vb;
    {
        size_t gA = base + ((size_t)(n0 + nnA) << 6) + c4A;
        size_t gB = base + ((size_t)(n0 + nnB) << 6) + c4B;
        ka = *reinterpret_cast<const float4*>(g_k2d + gA);
        va = *reinterpret_cast<const float4*>(g_v + gA);
        kb = *reinterpret_cast<const float4*>(g_k2d + gB);
        vb = *reinterpret_cast<const float4*>(g_v + gB);
    }

#pragma unroll 1
    for (int t = 0; t < 16; ++t) {
        __syncthreads();
        ks[(c4A + 0) * 33 + nnA] = ka.x;
        ks[(c4A + 1) * 33 + nnA] = ka.y;
        ks[(c4A + 2) * 33 + nnA] = ka.z;
        ks[(c4A + 3) * 33 + nnA] = ka.w;
        *reinterpret_cast<float4*>(vs + nnA * 68 + c4A) = va;
        ks[(c4B + 0) * 33 + nnB] = kb.x;
        ks[(c4B + 1) * 33 + nnB] = kb.y;
        ks[(c4B + 2) * 33 + nnB] = kb.z;
        ks[(c4B + 3) * 33 + nnB] = kb.w;
        *reinterpret_cast<float4*>(vs + nnB * 68 + c4B) = vb;
        if (t < 15) {
            const int nb = n0 + ((t + 1) << 5);
            size_t gA = base + ((size_t)(nb + nnA) << 6) + c4A;
            size_t gB = base + ((size_t)(nb + nnB) << 6) + c4B;
            ka = *reinterpret_cast<const float4*>(g_k2d + gA);
            va = *reinterpret_cast<const float4*>(g_v + gA);
            kb = *reinterpret_cast<const float4*>(g_k2d + gB);
            vb = *reinterpret_cast<const float4*>(g_v + gB);
        }
        __syncthreads();
        const float* kp = ks + c0 * 33;
#pragma unroll 4
        for (int nn = 0; nn < 32; ++nn) {
            ulonglong2 v01 = *reinterpret_cast<const ulonglong2*>(vs + nn * 68 + d0);
            float k0 = kp[nn], k1 = kp[33 + nn], k2 = kp[66 + nn], k3 = kp[99 + nn];
            u64 kk0 = dup2(k0), kk1 = dup2(k1), kk2 = dup2(k2), kk3 = dup2(k3);
            acc[0][0] = ffma2(kk0, v01.x, acc[0][0]); acc[0][1] = ffma2(kk0, v01.y, acc[0][1]);
            acc[1][0] = ffma2(kk1, v01.x, acc[1][0]); acc[1][1] = ffma2(kk1, v01.y, acc[1][1]);
            acc[2][0] = ffma2(kk2, v01.x, acc[2][0]); acc[2][1] = ffma2(kk2, v01.y, acc[2][1]);
            acc[3][0] = ffma2(kk3, v01.x, acc[3][0]); acc[3][1] = ffma2(kk3, v01.y, acc[3][1]);
        }
        if (tid < 64) {
            const float* cp = ks + tid * 33;
#pragma unroll 8
            for (int nn = 0; nn < 32; ++nn) { float u = cp[nn]; cssr = fmaf(u, u, cssr); }
        }
    }

    float* Mp = g_M + (b << 12);
#pragma unroll
    for (int i = 0; i < 4; ++i) {
        float2 a0 = unpack2(acc[i][0]), a1 = unpack2(acc[i][1]);
        atomicAdd(&Mp[(c0 + i) * 64 + d0 + 0], a0.x);
        atomicAdd(&Mp[(c0 + i) * 64 + d0 + 1], a0.y);
        atomicAdd(&Mp[(c0 + i) * 64 + d0 + 2], a1.x);
        atomicAdd(&Mp[(c0 + i) * 64 + d0 + 3], a1.y);
    }
    if (tid < 64) atomicAdd(&g_css[(b << 6) + tid], cssr);
}

// ---------------------------------------------------------------------------
// wcat v2: grid 64 = (b, jg). Block handles j in [8*jg, 8*jg+8).
//   k<64:   WcT[k][8jg+jj] = wln[(8jg+jj)][k]
//   k=64+c: WcT[64+c][j] = (sum_d M[c][d]*wln[j][d]) / (nrm_c*256)
__global__ __launch_bounds__(256) void essa_wcat(const float* __restrict__ wln) {
    __shared__ float sM[4096], sW[512], sInv[64];
    const int blk = blockIdx.x;
    const int b = blk >> 3, jg = blk & 7;
    const int j0 = jg << 3;
    const int tid = threadIdx.x;

    for (int i = tid; i < 4096; i += 256) sM[i] = g_M[(b << 12) + i];
    if (tid < 128) {
        int jj = tid >> 4, ck = (tid & 15) << 2;
        *(float4*)(sW + jj * 64 + ck) = *(const float4*)(wln + (j0 + jj) * 64 + ck);
    }
    if (tid < 64)
        sInv[tid] = 1.f / (fmaxf(sqrtf(g_css[(b << 6) + tid]), 1e-12f) * 256.f);
    __syncthreads();

    float* Wc = g_WcT + (b << 13);
    // transpose part: 512 elements, coalesced 8-float chunks per k
    for (int i = tid; i < 512; i += 256) {
        int k = i >> 3, jj = i & 7;
        Wc[k * 64 + j0 + jj] = sW[jj * 64 + k];
    }
    // product part: 512 outputs, 2 per thread
#pragma unroll
    for (int t = 0; t < 2; ++t) {
        int i = tid + (t << 8);
        int c = i >> 3, jj = i & 7;
        u64 s0 = 0, s1 = 0;
#pragma unroll
        for (int dd = 0; dd < 16; ++dd) {
            s0 = ffma2(lds_u64(sM + c * 64 + 4 * dd),     lds_u64(sW + jj * 64 + 4 * dd),     s0);
            s1 = ffma2(lds_u64(sM + c * 64 + 4 * dd + 2), lds_u64(sW + jj * 64 + 4 * dd + 2), s1);
        }
        Wc[(64 + c) * 64 + j0 + jj] = hsum2(s0, s1) * sInv[c];
    }
}

// ---------------------------------------------------------------------------
// out GEMM core (128 thr, j-packing, measured-best R11)
__device__ __forceinline__ void gemm_j(const float* __restrict__ A,
                                       const float* __restrict__ Wt,
                                       int tx, int ty, int k4lo, int k4hi,
                                       u64 acc[8][4]) {
#pragma unroll 2
    for (int k4 = k4lo; k4 < k4hi; ++k4) {
        ulonglong2 bt0[4], bt1[4];
#pragma unroll
        for (int kk = 0; kk < 4; ++kk) {
            bt0[kk] = lds_u128(Wt + (4 * k4 + kk) * 64 + 8 * ty);
            bt1[kk] = lds_u128(Wt + (4 * k4 + kk) * 64 + 8 * ty + 4);
        }
#pragma unroll
        for (int pp = 0; pp < 8; ++pp) {
            ulonglong2 a = lds_u128(A + (tx + 16 * pp) * 132 + 4 * k4);
            float2 al = unpack2(a.x), ah = unpack2(a.y);
            u64 d0 = dup2(al.x), d1 = dup2(al.y), d2 = dup2(ah.x), d3 = dup2(ah.y);
            acc[pp][0] = ffma2(d0, bt0[0].x, acc[pp][0]);
            acc[pp][1] = ffma2(d0, bt0[0].y, acc[pp][1]);
            acc[pp][2] = ffma2(d0, bt1[0].x, acc[pp][2]);
            acc[pp][3] = ffma2(d0, bt1[0].y, acc[pp][3]);
            acc[pp][0] = ffma2(d1, bt0[1].x, acc[pp][0]);
            acc[pp][1] = ffma2(d1, bt0[1].y, acc[pp][1]);
            acc[pp][2] = ffma2(d1, bt1[1].x, acc[pp][2]);
            acc[pp][3] = ffma2(d1, bt1[1].y, acc[pp][3]);
            acc[pp][0] = ffma2(d2, bt0[2].x, acc[pp][0]);
            acc[pp][1] = ffma2(d2, bt0[2].y, acc[pp][1]);
            acc[pp][2] = ffma2(d2, bt1[2].x, acc[pp][2]);
            acc[pp][3] = ffma2(d2, bt1[2].y, acc[pp][3]);
            acc[pp][0] = ffma2(d3, bt0[3].x, acc[pp][0]);
            acc[pp][1] = ffma2(d3, bt0[3].y, acc[pp][1]);
            acc[pp][2] = ffma2(d3, bt1[3].x, acc[pp][2]);
            acc[pp][3] = ffma2(d3, bt1[3].y, acc[pp][3]);
        }
    }
}

// ---------------------------------------------------------------------------
// out: K=128 GEMM out[n][j] = [v|q2n][n][:] . WcT[:][j] + bln[j]
// 4-way K-split cp.async pipeline (32 k per group).
// smem fl: A[128*132]=16896 | Wt[128*64]=8192 | sBl 64; C[128*66] overlays A
__global__ __launch_bounds__(128) void essa_out(const float* __restrict__ bln,
                                                float* __restrict__ out) {
    extern __shared__ float sm[];
    float* A   = sm;
    float* Wt  = sm + 16896;
    float* sBl = sm + 25088;
    float* C   = sm;   // overlay

    const int tid = threadIdx.x;
    const int tx = tid & 15, ty = tid >> 4;
    const int b = blockIdx.y;
    const int n0 = blockIdx.x << 7;
    const size_t base = (size_t)b << 22;
    const uint32_t A32 = smem_u32(A), Wt32 = smem_u32(Wt), B32 = smem_u32(sBl);
    const float* Ws = g_WcT + (b << 13);

    // 4 groups of 32 k: q=0,1 from v (cols 0..63), q=2,3 from q2n (cols 64..127)
#pragma unroll 1
    for (int q = 0; q < 4; ++q) {
        const float* srcA = (q < 2) ? g_v : g_q2n;
        const int co = (q & 1) << 5;                 // 0 or 32 within the source
        const int ao = (q << 5);                      // A column offset 0/32/64/96
        for (int i = tid; i < 1024; i += 128) {
            int px = i >> 3, ck = (i & 7) << 2;
            cpa16(A32 + (px * 132 + ao + ck) * 4,
                  srcA + base + ((size_t)(n0 + px) << 6) + co + ck);
        }
        for (int i = tid; i < 512; i += 128) {
            int k = i >> 4, ck = (i & 15) << 2;
            cpa16(Wt32 + ((ao + k) * 64 + ck) * 4, Ws + (ao + k) * 64 + ck);
        }
        if (q == 0 && tid < 16) cpa16(B32 + tid * 16, bln + tid * 4);
        CPA_COMMIT();
    }

    u64 acc[8][4];
#pragma unroll
    for (int pp = 0; pp < 8; ++pp)
#pragma unroll
        for (int jq = 0; jq < 4; ++jq) acc[pp][jq] = 0;

    CPA_WAIT(3);
    __syncthreads();
    gemm_j(A, Wt, tx, ty, 0, 8, acc);
    CPA_WAIT(2);
    __syncthreads();
    gemm_j(A, Wt, tx, ty, 8, 16, acc);
    CPA_WAIT(1);
    __syncthreads();
    gemm_j(A, Wt, tx, ty, 16, 24, acc);
    CPA_WAIT(0);
    __syncthreads();
    gemm_j(A, Wt, tx, ty, 24, 32, acc);
    __syncthreads();   // A reads done -> C overlay

#pragma unroll
    for (int pp = 0; pp < 8; ++pp)
#pragma unroll
        for (int jq = 0; jq < 4; ++jq)
            *(u64*)(C + (tx + 16 * pp) * 66 + 8 * ty + 2 * jq) = acc[pp][jq];
    __syncthreads();

    for (int i = tid; i < 8192; i += 128) {
        int j = i >> 7, px = i & 127;
        out[base + ((size_t)j << 16) + n0 + px] = C[px * 66 + j] + sBl[j];
    }
}

// ---------------------------------------------------------------------------
extern "C" void kernel_launch(void* const* d_in, const int* in_sizes, int n_in,
                              void* d_out, int out_size) {
    const float* x    = (const float*)d_in[0];
    const float* wqkv = (const float*)d_in[1];
    const float* bqkv = (const float*)d_in[2];
    const float* wln  = (const float*)d_in[3];
    const float* bln  = (const float*)d_in[4];
    float* out = (float*)d_out;

    cudaFuncSetAttribute(essa_qkv, cudaFuncAttributeMaxDynamicSharedMemorySize, 100608);
    cudaFuncSetAttribute(essa_out, cudaFuncAttributeMaxDynamicSharedMemorySize, 100608);

    dim3 gridQ(NPIX / 128, NBAT);
    essa_qkv<<<gridQ, 256, 100608>>>(x, wqkv, bqkv);

    dim3 gridM(NPIX / 512, NBAT);
    essa_kvacc<<<gridM, 256>>>();

    essa_wcat<<<64, 256>>>(wln);

    essa_out<<<gridQ, 128, 100608>>>(bln, out);
}

// round 17
// speedup vs baseline: 1.0786x; 1.0064x over previous
#include <cuda_runtime.h>
#include <cstdint>

// ESSAttn: b=8, C=64, H=W=256, N=65536
// x, out: [b][C][N]  (b<<22 | c<<16 | n)
// scratch q2n,k2d,v: [b][N][C]  (b<<22 | n<<6 | c)

#define NPIX 65536
#define NBAT 8

typedef unsigned long long u64;

// ---------------- scratch ----------------
__device__ float g_q2n[(size_t)NBAT * 64 * NPIX];
__device__ float g_k2d[(size_t)NBAT * 64 * NPIX];
__device__ float g_v  [(size_t)NBAT * 64 * NPIX];
__device__ float g_M  [NBAT * 64 * 64];
__device__ float g_css[NBAT * 64];
__device__ float g_WcT[NBAT * 128 * 64];   // [b][k][j] k-major concat weight (out)

// ---------------- packed fp32 + async helpers ----------------
__device__ __forceinline__ u64 ffma2(u64 a, u64 b, u64 c) {
    u64 d;
    asm("fma.rn.f32x2 %0, %1, %2, %3;" : "=l"(d) : "l"(a), "l"(b), "l"(c));
    return d;
}
__device__ __forceinline__ u64 fadd2(u64 a, u64 b) {
    u64 d;
    asm("add.rn.f32x2 %0, %1, %2;" : "=l"(d) : "l"(a), "l"(b));
    return d;
}
__device__ __forceinline__ float2 unpack2(u64 v) {
    float lo, hi;
    asm("mov.b64 {%0, %1}, %2;" : "=f"(lo), "=f"(hi) : "l"(v));
    return make_float2(lo, hi);
}
__device__ __forceinline__ u64 dup2(float f) {
    u64 d;
    asm("mov.b64 %0, {%1, %1};" : "=l"(d) : "f"(f));
    return d;
}
__device__ __forceinline__ float hsum2(u64 a, u64 b) {
    float2 r = unpack2(fadd2(a, b));
    return r.x + r.y;
}
__device__ __forceinline__ u64 lds_u64(const float* p) {
    return *reinterpret_cast<const u64*>(p);
}
__device__ __forceinline__ ulonglong2 lds_u128(const float* p) {
    return *reinterpret_cast<const ulonglong2*>(p);
}
__device__ __forceinline__ uint32_t smem_u32(const void* p) {
    uint32_t a;
    asm("{ .reg .u64 t; cvta.to.shared.u64 t, %1; cvt.u32.u64 %0, t; }" : "=r"(a) : "l"(p));
    return a;
}
__device__ __forceinline__ void cpa16(uint32_t dst, const float* src) {
    asm volatile("cp.async.cg.shared.global [%0], [%1], 16;" :: "r"(dst), "l"(src));
}
#define CPA_COMMIT() asm volatile("cp.async.commit_group;" ::: "memory")
#define CPA_WAIT(n)  asm volatile("cp.async.wait_group %0;" :: "n"(n) : "memory")

// ---------------------------------------------------------------------------
// qkv GEMM core (256 thr, px-packing): tx=tid&31, ty=tid>>5 (warp==ty).
// acc[pq][jj] = (out(px0), out(px0+1)), px0 = 2*(tx+32*pq), j = 8*ty+jj.
// A[k][px] pad 132, W[j][k] rows of 64. B loads are whole-warp broadcasts.
__device__ __forceinline__ void gemm_px(const float* __restrict__ A,
                                        const float* __restrict__ W,
                                        int tx, int ty, u64 acc[2][8]) {
#pragma unroll
    for (int pq = 0; pq < 2; ++pq)
#pragma unroll
        for (int jj = 0; jj < 8; ++jj) acc[pq][jj] = 0;
#pragma unroll 2
    for (int k4 = 0; k4 < 16; ++k4) {
        u64 av[4][2];   // [kk][pq]
#pragma unroll
        for (int kk = 0; kk < 4; ++kk)
#pragma unroll
            for (int pq = 0; pq < 2; ++pq)
                av[kk][pq] = lds_u64(A + (4 * k4 + kk) * 132 + 2 * (tx + 32 * pq));
#pragma unroll
        for (int jj = 0; jj < 8; ++jj) {
            ulonglong2 bb = lds_u128(W + (8 * ty + jj) * 64 + 4 * k4);
            float2 bl = unpack2(bb.x), bh = unpack2(bb.y);
            u64 d0 = dup2(bl.x), d1 = dup2(bl.y), d2 = dup2(bh.x), d3 = dup2(bh.y);
#pragma unroll
            for (int pq = 0; pq < 2; ++pq) {
                acc[pq][jj] = ffma2(av[0][pq], d0, acc[pq][jj]);
                acc[pq][jj] = ffma2(av[1][pq], d1, acc[pq][jj]);
                acc[pq][jj] = ffma2(av[2][pq], d2, acc[pq][jj]);
                acc[pq][jj] = ffma2(av[3][pq], d3, acc[pq][jj]);
            }
        }
    }
}

// ---------------------------------------------------------------------------
// qkv: 256 thr/CTA, 128 px, 3 passes of 64 outputs (R13 measured-best, exact).
// smem fl: A[64*132]=8448 | W0 4096 | W1 4096 | C[64*130]=8320 | sB 192 -> 100608 B
__global__ __launch_bounds__(256) void essa_qkv(const float* __restrict__ x,
                                                const float* __restrict__ wqkv,
                                                const float* __restrict__ bqkv) {
    extern __shared__ float sm[];
    float* A  = sm;
    float* W0 = sm + 8448;
    float* W1 = sm + 12544;
    float* C  = sm + 16640;
    float* sB = sm + 24960;

    const int tid = threadIdx.x;
    const int tx = tid & 31, ty = tid >> 5;
    const int b = blockIdx.y;
    const int n0 = blockIdx.x << 7;
    const size_t base = (size_t)b << 22;
    const uint32_t A32 = smem_u32(A), W032 = smem_u32(W0), W132 = smem_u32(W1);

    if (blockIdx.x == 0 && b == 0) {
        for (int i = tid; i < NBAT * 64 * 64; i += 256) g_M[i] = 0.f;
        for (int i = tid; i < NBAT * 64; i += 256) g_css[i] = 0.f;
    }

    // G0: A rows (row copy from x [c][n]; 64 rows x 32 chunks) + W(Q)
    for (int i = tid; i < 2048; i += 256) {
        int k = i >> 5, ck = (i & 31) << 2;
        cpa16(A32 + (k * 132 + ck) * 4, x + base + ((size_t)k << 16) + n0 + ck);
    }
    for (int i = tid; i < 1024; i += 256) {
        int j = i >> 4, ck = (i & 15) << 2;
        cpa16(W032 + (j * 64 + ck) * 4, wqkv + j * 64 + ck);
    }
    CPA_COMMIT();
    // G1: W(K)
    for (int i = tid; i < 1024; i += 256) {
        int j = i >> 4, ck = (i & 15) << 2;
        cpa16(W132 + (j * 64 + ck) * 4, wqkv + 4096 + j * 64 + ck);
    }
    CPA_COMMIT();
    if (tid < 48) *(float4*)(sB + tid * 4) = *(const float4*)(bqkv + tid * 4);
    CPA_WAIT(1);
    __syncthreads();

    // stats mapping: 2 threads per pixel (partner = tid^1, same warp)
    const int spx = tid >> 1;
    const int h = tid & 1;

    u64 acc[2][8];

#pragma unroll 1
    for (int pass = 0; pass < 3; ++pass) {
        gemm_px(A, (pass == 1) ? W1 : W0, tx, ty, acc);

        if (pass < 2) {
            __syncthreads();   // all warps done reading current W buffer
            if (pass == 0) {   // V weights -> W0
                for (int i = tid; i < 1024; i += 256) {
                    int j = i >> 4, ck = (i & 15) << 2;
                    cpa16(W032 + (j * 64 + ck) * 4, wqkv + 8192 + j * 64 + ck);
                }
                CPA_COMMIT();
            }
            // stage C[j][px] pad 130 (STS.64)
#pragma unroll
            for (int jj = 0; jj < 8; ++jj)
#pragma unroll
                for (int pq = 0; pq < 2; ++pq)
                    *(u64*)(C + (8 * ty + jj) * 130 + 2 * (tx + 32 * pq)) = acc[pq][jj];
            __syncthreads();

            // stats: thread handles channels h*32..h*32+31 of pixel spx
            {
                const int boff = pass * 64, j0 = h << 5;
                const size_t rownc = base + ((size_t)(n0 + spx) << 6);
                float rv[32];
                float part = 0.f;
#pragma unroll
                for (int t = 0; t < 32; ++t) {
                    rv[t] = C[(j0 + t) * 130 + spx] + sB[boff + j0 + t];
                    part += rv[t];
                }
                float mean = (part + __shfl_xor_sync(0xFFFFFFFFu, part, 1)) * (1.f / 64.f);
                float ss = 0.f;
#pragma unroll
                for (int t = 0; t < 32; ++t) {
                    float u = rv[t] - mean;
                    u = u * u;
                    rv[t] = u;
                    ss += u;
                }
                ss += __shfl_xor_sync(0xFFFFFFFFu, ss, 1);
                float inv = 1.f / (ss + 1e-7f);
                float scale;
                if (pass == 0) {
                    float nr = 0.f;
#pragma unroll
                    for (int t = 0; t < 32; ++t) {
                        float u = rv[t] * inv;
                        nr = fmaf(u, u, nr);
                    }
                    nr += __shfl_xor_sync(0xFFFFFFFFu, nr, 1);
                    scale = inv / fmaxf(sqrtf(nr), 1e-12f);
                } else {
                    scale = inv;
                }
                float* dst = (pass == 0 ? g_q2n : g_k2d) + rownc + j0;
#pragma unroll
                for (int t = 0; t < 8; ++t)
                    reinterpret_cast<float4*>(dst)[t] =
                        make_float4(rv[4 * t] * scale, rv[4 * t + 1] * scale,
                                    rv[4 * t + 2] * scale, rv[4 * t + 3] * scale);
            }
            if (pass == 0) { CPA_WAIT(1); } else { CPA_WAIT(0); }
            __syncthreads();
        } else {
            // V: assemble float4 rows from packed acc -> g_v [n][c]
            float bs[8];
#pragma unroll
            for (int jj = 0; jj < 8; ++jj) bs[jj] = sB[128 + 8 * ty + jj];
#pragma unroll
            for (int pq = 0; pq < 2; ++pq) {
                const int n = n0 + 2 * (tx + 32 * pq);
                float* dst = g_v + base + ((size_t)n << 6) + 8 * ty;
                float2 u0 = unpack2(acc[pq][0]), u1 = unpack2(acc[pq][1]);
                float2 u2 = unpack2(acc[pq][2]), u3 = unpack2(acc[pq][3]);
                float2 u4 = unpack2(acc[pq][4]), u5 = unpack2(acc[pq][5]);
                float2 u6 = unpack2(acc[pq][6]), u7 = unpack2(acc[pq][7]);
                *(float4*)(dst)      = make_float4(u0.x + bs[0], u1.x + bs[1], u2.x + bs[2], u3.x + bs[3]);
                *(float4*)(dst + 4)  = make_float4(u4.x + bs[4], u5.x + bs[5], u6.x + bs[6], u7.x + bs[7]);
                *(float4*)(dst + 64) = make_float4(u0.y + bs[0], u1.y + bs[1], u2.y + bs[2], u3.y + bs[3]);
                *(float4*)(dst + 68) = make_float4(u4.y + bs[4], u5.y + bs[5], u6.y + bs[6], u7.y + bs[7]);
            }
        }
    }
}

// ---------------------------------------------------------------------------
// kvacc: reg-prefetch, FFMA2 (unchanged)
__global__ __launch_bounds__(256) void essa_kvacc() {
    const int b = blockIdx.y;
    const int n0 = blockIdx.x << 9;
    const size_t base = (size_t)b << 22;

    __shared__ float ks[64 * 33];
    __shared__ __align__(16) float vs[32 * 68];

    const int tid = threadIdx.x;
    const int ty = tid >> 4, tx = tid & 15;
    const int c0 = ty << 2, d0 = tx << 2;

    const int nnA = tid >> 4, c4A = (tid & 15) << 2;
    const int i1 = tid + 256;
    const int nnB = i1 >> 4, c4B = (i1 & 15) << 2;

    u64 acc[4][2];
#pragma unroll
    for (int i = 0; i < 4; ++i) { acc[i][0] = 0; acc[i][1] = 0; }
    float cssr = 0.f;

    float4 ka, va, kb, vb;
    {
        size_t gA = base + ((size_t)(n0 + nnA) << 6) + c4A;
        size_t gB = base + ((size_t)(n0 + nnB) << 6) + c4B;
        ka = *reinterpret_cast<const float4*>(g_k2d + gA);
        va = *reinterpret_cast<const float4*>(g_v + gA);
        kb = *reinterpret_cast<const float4*>(g_k2d + gB);
        vb = *reinterpret_cast<const float4*>(g_v + gB);
    }

#pragma unroll 1
    for (int t = 0; t < 16; ++t) {
        __syncthreads();
        ks[(c4A + 0) * 33 + nnA] = ka.x;
        ks[(c4A + 1) * 33 + nnA] = ka.y;
        ks[(c4A + 2) * 33 + nnA] = ka.z;
        ks[(c4A + 3) * 33 + nnA] = ka.w;
        *reinterpret_cast<float4*>(vs + nnA * 68 + c4A) = va;
        ks[(c4B + 0) * 33 + nnB] = kb.x;
        ks[(c4B + 1) * 33 + nnB] = kb.y;
        ks[(c4B + 2) * 33 + nnB] = kb.z;
        ks[(c4B + 3) * 33 + nnB] = kb.w;
        *reinterpret_cast<float4*>(vs + nnB * 68 + c4B) = vb;
        if (t < 15) {
            const int nb = n0 + ((t + 1) << 5);
            size_t gA = base + ((size_t)(nb + nnA) << 6) + c4A;
            size_t gB = base + ((size_t)(nb + nnB) << 6) + c4B;
            ka = *reinterpret_cast<const float4*>(g_k2d + gA);
            va = *reinterpret_cast<const float4*>(g_v + gA);
            kb = *reinterpret_cast<const float4*>(g_k2d + gB);
            vb = *reinterpret_cast<const float4*>(g_v + gB);
        }
        __syncthreads();
        const float* kp = ks + c0 * 33;
#pragma unroll 4
        for (int nn = 0; nn < 32; ++nn) {
            ulonglong2 v01 = *reinterpret_cast<const ulonglong2*>(vs + nn * 68 + d0);
            float k0 = kp[nn], k1 = kp[33 + nn], k2 = kp[66 + nn], k3 = kp[99 + nn];
            u64 kk0 = dup2(k0), kk1 = dup2(k1), kk2 = dup2(k2), kk3 = dup2(k3);
            acc[0][0] = ffma2(kk0, v01.x, acc[0][0]); acc[0][1] = ffma2(kk0, v01.y, acc[0][1]);
            acc[1][0] = ffma2(kk1, v01.x, acc[1][0]); acc[1][1] = ffma2(kk1, v01.y, acc[1][1]);
            acc[2][0] = ffma2(kk2, v01.x, acc[2][0]); acc[2][1] = ffma2(kk2, v01.y, acc[2][1]);
            acc[3][0] = ffma2(kk3, v01.x, acc[3][0]); acc[3][1] = ffma2(kk3, v01.y, acc[3][1]);
        }
        if (tid < 64) {
            const float* cp = ks + tid * 33;
#pragma unroll 8
            for (int nn = 0; nn < 32; ++nn) { float u = cp[nn]; cssr = fmaf(u, u, cssr); }
        }
    }

    float* Mp = g_M + (b << 12);
#pragma unroll
    for (int i = 0; i < 4; ++i) {
        float2 a0 = unpack2(acc[i][0]), a1 = unpack2(acc[i][1]);
        atomicAdd(&Mp[(c0 + i) * 64 + d0 + 0], a0.x);
        atomicAdd(&Mp[(c0 + i) * 64 + d0 + 1], a0.y);
        atomicAdd(&Mp[(c0 + i) * 64 + d0 + 2], a1.x);
        atomicAdd(&Mp[(c0 + i) * 64 + d0 + 3], a1.y);
    }
    if (tid < 64) atomicAdd(&g_css[(b << 6) + tid], cssr);
}

// ---------------------------------------------------------------------------
// wcat v2 (R16 measured win): grid 64 = (b, jg). Block handles j in [8jg, 8jg+8).
__global__ __launch_bounds__(256) void essa_wcat(const float* __restrict__ wln) {
    __shared__ float sM[4096], sW[512], sInv[64];
    const int blk = blockIdx.x;
    const int b = blk >> 3, jg = blk & 7;
    const int j0 = jg << 3;
    const int tid = threadIdx.x;

    for (int i = tid; i < 4096; i += 256) sM[i] = g_M[(b << 12) + i];
    if (tid < 128) {
        int jj = tid >> 4, ck = (tid & 15) << 2;
        *(float4*)(sW + jj * 64 + ck) = *(const float4*)(wln + (j0 + jj) * 64 + ck);
    }
    if (tid < 64)
        sInv[tid] = 1.f / (fmaxf(sqrtf(g_css[(b << 6) + tid]), 1e-12f) * 256.f);
    __syncthreads();

    float* Wc = g_WcT + (b << 13);
    for (int i = tid; i < 512; i += 256) {
        int k = i >> 3, jj = i & 7;
        Wc[k * 64 + j0 + jj] = sW[jj * 64 + k];
    }
#pragma unroll
    for (int t = 0; t < 2; ++t) {
        int i = tid + (t << 8);
        int c = i >> 3, jj = i & 7;
        u64 s0 = 0, s1 = 0;
#pragma unroll
        for (int dd = 0; dd < 16; ++dd) {
            s0 = ffma2(lds_u64(sM + c * 64 + 4 * dd),     lds_u64(sW + jj * 64 + 4 * dd),     s0);
            s1 = ffma2(lds_u64(sM + c * 64 + 4 * dd + 2), lds_u64(sW + jj * 64 + 4 * dd + 2), s1);
        }
        Wc[(64 + c) * 64 + j0 + jj] = hsum2(s0, s1) * sInv[c];
    }
}

// ---------------------------------------------------------------------------
// out GEMM core (128 thr, j-packing, measured-best R11/R13)
__device__ __forceinline__ void gemm_j(const float* __restrict__ A,
                                       const float* __restrict__ Wt,
                                       int tx, int ty, int k4lo, int k4hi,
                                       u64 acc[8][4]) {
#pragma unroll 2
    for (int k4 = k4lo; k4 < k4hi; ++k4) {
        ulonglong2 bt0[4], bt1[4];
#pragma unroll
        for (int kk = 0; kk < 4; ++kk) {
            bt0[kk] = lds_u128(Wt + (4 * k4 + kk) * 64 + 8 * ty);
            bt1[kk] = lds_u128(Wt + (4 * k4 + kk) * 64 + 8 * ty + 4);
        }
#pragma unroll
        for (int pp = 0; pp < 8; ++pp) {
            ulonglong2 a = lds_u128(A + (tx + 16 * pp) * 132 + 4 * k4);
            float2 al = unpack2(a.x), ah = unpack2(a.y);
            u64 d0 = dup2(al.x), d1 = dup2(al.y), d2 = dup2(ah.x), d3 = dup2(ah.y);
            acc[pp][0] = ffma2(d0, bt0[0].x, acc[pp][0]);
            acc[pp][1] = ffma2(d0, bt0[0].y, acc[pp][1]);
            acc[pp][2] = ffma2(d0, bt1[0].x, acc[pp][2]);
            acc[pp][3] = ffma2(d0, bt1[0].y, acc[pp][3]);
            acc[pp][0] = ffma2(d1, bt0[1].x, acc[pp][0]);
            acc[pp][1] = ffma2(d1, bt0[1].y, acc[pp][1]);
            acc[pp][2] = ffma2(d1, bt1[1].x, acc[pp][2]);
            acc[pp][3] = ffma2(d1, bt1[1].y, acc[pp][3]);
            acc[pp][0] = ffma2(d2, bt0[2].x, acc[pp][0]);
            acc[pp][1] = ffma2(d2, bt0[2].y, acc[pp][1]);
            acc[pp][2] = ffma2(d2, bt1[2].x, acc[pp][2]);
            acc[pp][3] = ffma2(d2, bt1[2].y, acc[pp][3]);
            acc[pp][0] = ffma2(d3, bt0[3].x, acc[pp][0]);
            acc[pp][1] = ffma2(d3, bt0[3].y, acc[pp][1]);
            acc[pp][2] = ffma2(d3, bt1[3].x, acc[pp][2]);
            acc[pp][3] = ffma2(d3, bt1[3].y, acc[pp][3]);
        }
    }
}

// ---------------------------------------------------------------------------
// out: K=128 GEMM out[n][j] = [v|q2n][n][:] . WcT[:][j] + bln[j]  (R13-exact)
// smem fl: A[128*132]=16896 | Wt[128*64]=8192 | sBl 64; C[128*66] overlays A
__global__ __launch_bounds__(128) void essa_out(const float* __restrict__ bln,
                                                float* __restrict__ out) {
    extern __shared__ float sm[];
    float* A   = sm;
    float* Wt  = sm + 16896;
    float* sBl = sm + 25088;
    float* C   = sm;   // overlay

    const int tid = threadIdx.x;
    const int tx = tid & 15, ty = tid >> 4;
    const int b = blockIdx.y;
    const int n0 = blockIdx.x << 7;
    const size_t base = (size_t)b << 22;
    const uint32_t A32 = smem_u32(A), Wt32 = smem_u32(Wt), B32 = smem_u32(sBl);
    const float* Ws = g_WcT + (b << 13);

    for (int i = tid; i < 2048; i += 128) {
        int px = i >> 4, ck = (i & 15) << 2;
        cpa16(A32 + (px * 132 + ck) * 4, g_v + base + ((size_t)(n0 + px) << 6) + ck);
    }
    for (int i = tid; i < 1024; i += 128) {
        int k = i >> 4, ck = (i & 15) << 2;
        cpa16(Wt32 + (k * 64 + ck) * 4, Ws + k * 64 + ck);
    }
    if (tid < 16) cpa16(B32 + tid * 16, bln + tid * 4);
    CPA_COMMIT();
    for (int i = tid; i < 2048; i += 128) {
        int px = i >> 4, ck = (i & 15) << 2;
        cpa16(A32 + (px * 132 + 64 + ck) * 4, g_q2n + base + ((size_t)(n0 + px) << 6) + ck);
    }
    for (int i = tid; i < 1024; i += 128) {
        int k = i >> 4, ck = (i & 15) << 2;
        cpa16(Wt32 + ((64 + k) * 64 + ck) * 4, Ws + (64 + k) * 64 + ck);
    }
    CPA_COMMIT();

    u64 acc[8][4];
#pragma unroll
    for (int pp = 0; pp < 8; ++pp)
#pragma unroll
        for (int jq = 0; jq < 4; ++jq) acc[pp][jq] = 0;

    CPA_WAIT(1);
    __syncthreads();
    gemm_j(A, Wt, tx, ty, 0, 16, acc);
    CPA_WAIT(0);
    __syncthreads();
    gemm_j(A, Wt, tx, ty, 16, 32, acc);
    __syncthreads();   // A reads done -> C overlay

#pragma unroll
    for (int pp = 0; pp < 8; ++pp)
#pragma unroll
        for (int jq = 0; jq < 4; ++jq)
            *(u64*)(C + (tx + 16 * pp) * 66 + 8 * ty + 2 * jq) = acc[pp][jq];
    __syncthreads();

    for (int i = tid; i < 8192; i += 128) {
        int j = i >> 7, px = i & 127;
        out[base + ((size_t)j << 16) + n0 + px] = C[px * 66 + j] + sBl[j];
    }
}

// ---------------------------------------------------------------------------
extern "C" void kernel_launch(void* const* d_in, const int* in_sizes, int n_in,
                              void* d_out, int out_size) {
    const float* x    = (const float*)d_in[0];
    const float* wqkv = (const float*)d_in[1];
    const float* bqkv = (const float*)d_in[2];
    const float* wln  = (const float*)d_in[3];
    const float* bln  = (const float*)d_in[4];
    float* out = (float*)d_out;

    cudaFuncSetAttribute(essa_qkv, cudaFuncAttributeMaxDynamicSharedMemorySize, 100608);
    cudaFuncSetAttribute(essa_out, cudaFuncAttributeMaxDynamicSharedMemorySize, 100608);

    dim3 gridQ(NPIX / 128, NBAT);
    essa_qkv<<<gridQ, 256, 100608>>>(x, wqkv, bqkv);

    dim3 gridM(NPIX / 512, NBAT);
    essa_kvacc<<<gridM, 256>>>();

    essa_wcat<<<64, 256>>>(wln);

    essa_out<<<gridQ, 128, 100608>>>(bln, out);
}